// round 16
// baseline (speedup 1.0000x reference)
#include <cuda_runtime.h>
#include <cstdint>

// Problem constants (fixed by the benchmark's setup_inputs).
#define BS      32
#define M       256
#define N       512
#define ITERS   1000
#define ALPHA   0.02f
#define BETA    0.02f

#define CLUSTER 4
#define ROWS    (M / CLUSTER)      // 64 rows of A per CTA
#define THREADS 512
#define EXPECT_BYTES (CLUSTER * N * 4)   // 8192 bytes per exchange phase

__device__ __forceinline__ uint32_t smem_u32(const void* p) {
    uint32_t a;
    asm("{ .reg .u64 t; cvta.to.shared.u64 t, %1; cvt.u32.u64 %0, t; }"
        : "=r"(a) : "l"(p));
    return a;
}

__device__ __forceinline__ uint32_t mapa_rank(uint32_t addr, uint32_t rank) {
    uint32_t o;
    asm("mapa.shared::cluster.u32 %0, %1, %2;" : "=r"(o) : "r"(addr), "r"(rank));
    return o;
}

__device__ __forceinline__ void cluster_sync_() {
    asm volatile("barrier.cluster.arrive.aligned;" ::: "memory");
    asm volatile("barrier.cluster.wait.aligned;" ::: "memory");
}

// Remote SMEM store with mbarrier tx-completion (Hopper+ st.async).
__device__ __forceinline__ void st_async_f32(uint32_t raddr, float v, uint32_t rmbar) {
    asm volatile(
        "st.async.shared::cluster.mbarrier::complete_tx::bytes.f32 [%0], %1, [%2];"
        :: "r"(raddr), "f"(v), "r"(rmbar) : "memory");
}

__device__ __forceinline__ void mbar_init(uint32_t addr, uint32_t count) {
    asm volatile("mbarrier.init.shared.b64 [%0], %1;" :: "r"(addr), "r"(count) : "memory");
}

__device__ __forceinline__ void mbar_arrive_expect_tx(uint32_t addr, uint32_t bytes) {
    asm volatile("mbarrier.arrive.expect_tx.shared.b64 _, [%0], %1;"
                 :: "r"(addr), "r"(bytes) : "memory");
}

// Cluster-scope acquire wait (following LDS reads must see remote st.async data).
__device__ __forceinline__ void mbar_wait(uint32_t addr, uint32_t parity) {
    uint32_t done;
    asm volatile(
        "{\n\t.reg .pred p;\n\t"
        "mbarrier.try_wait.parity.acquire.cluster.shared::cta.b64 p, [%1], %2, 0x989680;\n\t"
        "selp.b32 %0, 1, 0, p;\n\t}"
        : "=r"(done) : "r"(addr), "r"(parity) : "memory");
    while (!done) {
        asm volatile(
            "{\n\t.reg .pred p;\n\t"
            "mbarrier.try_wait.parity.acquire.cluster.shared::cta.b64 p, [%1], %2, 0x989680;\n\t"
            "selp.b32 %0, 1, 0, p;\n\t}"
            : "=r"(done) : "r"(addr), "r"(parity) : "memory");
    }
}

// ---- packed f32x2 helpers (Blackwell FFMA2 via PTX) ----
__device__ __forceinline__ uint64_t pk2(float lo, float hi) {
    uint64_t r;
    asm("mov.b64 %0, {%1, %2};" : "=l"(r) : "f"(lo), "f"(hi));
    return r;
}
__device__ __forceinline__ void unpk2(uint64_t v, float& lo, float& hi) {
    asm("mov.b64 {%0, %1}, %2;" : "=f"(lo), "=f"(hi) : "l"(v));
}
__device__ __forceinline__ uint64_t fma2(uint64_t a, uint64_t b, uint64_t c) {
    uint64_t d;
    asm("fma.rn.f32x2 %0, %1, %2, %3;" : "=l"(d) : "l"(a), "l"(b), "l"(c));
    return d;
}

__global__ void __cluster_dims__(CLUSTER, 1, 1) __launch_bounds__(THREADS, 1)
pdhg_kernel(const float* __restrict__ A, const float* __restrict__ b,
            float* __restrict__ out)
{
    __shared__ float zs[4 * N];            // 4 row-group partials per col (8 KB)
    __shared__ float zin[2][CLUSTER][N];   // incoming partials          (16 KB)
    __shared__ float wv[N];                // w = 2*x_new - x_old
    __shared__ float us[4 * 16 * 5];       // pass2 cross-warp row partials (pad 5)
    __shared__ __align__(8) unsigned long long mbar[2];

    const int tid   = threadIdx.x;
    const int batch = blockIdx.x / CLUSTER;
    const int rank  = blockIdx.x % CLUSTER;
    const int lane  = tid & 31;
    const int wrp   = tid >> 5;
    const int i     = wrp >> 2;            // row group: rows 16i .. 16i+15
    const int j     = wrp & 3;             // col group: cols 128j .. 128j+127
    const int rl    = (lane >> 1) & 15;    // this lane's owned row (dup x2)

    // ---- A tile into registers: 16 rows x 4 cols (float4 block at lane).
    uint64_t Apk[16][2];
    {
        const float4* Ag = reinterpret_cast<const float4*>(
            A + (size_t)batch * (M * N));
        const int base = (rank * ROWS + 16 * i) * 128 + 32 * j + lane;
        #pragma unroll
        for (int r = 0; r < 16; ++r) {
            const float4 v = Ag[base + r * 128];
            Apk[r][0] = pk2(v.x, v.y);
            Apk[r][1] = pk2(v.z, v.w);
        }
    }

    // ---- u (1 reg, row rl of group i), b likewise ----
    float ureg = 0.0f;
    const float breg = b[batch * M + rank * ROWS + 16 * i + rl];

    float xreg = 0.0f;   // this thread owns column `tid` of the replicated x

    // ---- mbarrier + remote address setup ----
    const uint32_t mbar_base = smem_u32(mbar);
    const uint32_t zin_base  = smem_u32(zin);
    if (tid == 0) {
        mbar_init(mbar_base, 1);
        mbar_init(mbar_base + 8, 1);
    }
    uint32_t zin_r[CLUSTER], mbar_r[CLUSTER];
    #pragma unroll
    for (int p = 0; p < CLUSTER; ++p) {
        zin_r[p]  = mapa_rank(zin_base, p) + ((uint32_t)(rank * N + tid) * 4u);
        mbar_r[p] = mapa_rank(mbar_base, p);
    }
    __syncthreads();
    cluster_sync_();   // all ranks' mbarriers initialized before any st.async

    // Pre-arm both buffers (they are armed-after-consume inside the loop).
    if (tid == 0) {
        mbar_arrive_expect_tx(mbar_base,     EXPECT_BYTES);
        mbar_arrive_expect_tx(mbar_base + 8, EXPECT_BYTES);
    }

    float4* zs4 = reinterpret_cast<float4*>(zs);
    const float4* W4 = reinterpret_cast<const float4*>(wv);
    uint32_t parity[2] = {0u, 0u};

    for (int it = 0; it < ITERS; ++it) {
        const int buf = it & 1;
        const uint32_t buf_off = (uint32_t)(buf * CLUSTER * N) * 4u;

        // ========== Pass 1: group partial z[c] = sum_{16 rows} A[m][c]*u[m]
        {
            uint64_t pz0 = 0ull, pz1 = 0ull;
            #pragma unroll
            for (int r = 0; r < 16; ++r) {
                const float ur = __shfl_sync(0xffffffffu, ureg, r << 1);
                const uint64_t u2 = pk2(ur, ur);
                pz0 = fma2(Apk[r][0], u2, pz0);
                pz1 = fma2(Apk[r][1], u2, pz1);
            }
            float x0, y0, x1, y1;
            unpk2(pz0, x0, y0);
            unpk2(pz1, x1, y1);
            zs4[i * 128 + 32 * j + lane] = make_float4(x0, y0, x1, y1);
        }
        __syncthreads();   // bar1

        // 4-way reduction over row groups, then push partial to all 4 ranks.
        {
            const float z = (zs[tid] + zs[N + tid]) +
                            (zs[2 * N + tid] + zs[3 * N + tid]);
            #pragma unroll
            for (int p = 0; p < CLUSTER; ++p)
                st_async_f32(zin_r[p] + buf_off, z, mbar_r[p] + 8u * buf);
        }

        // ========== Wait for all 4 partials, x update, re-arm buffer =======
        mbar_wait(mbar_base + 8u * buf, parity[buf]);
        parity[buf] ^= 1u;
        {
            const float* zb = &zin[buf][0][0];
            const float ztot = (zb[tid] + zb[N + tid]) +
                               (zb[2 * N + tid] + zb[3 * N + tid]);

            const float v  = fmaf(-ALPHA, ztot, xreg);
            const float xn = fmaxf(v - ALPHA, 0.0f) - fmaxf(-v - ALPHA, 0.0f);
            wv[tid] = 2.0f * xn - xreg;
            xreg = xn;
        }
        if (tid == 0)   // re-arm this buffer for its next use (it+2):
            mbar_arrive_expect_tx(mbar_base + 8u * buf, EXPECT_BYTES);
        __syncthreads();   // bar2

        // ========== Pass 2: y[m] = A[m]·w, segmented butterfly reduce ======
        {
            const float4 wq = W4[32 * j + lane];
            const uint64_t w0 = pk2(wq.x, wq.y);
            const uint64_t w1 = pk2(wq.z, wq.w);

            float vals[16];
            #pragma unroll
            for (int r = 0; r < 16; ++r) {
                const uint64_t acc = fma2(Apk[r][0], w0, fma2(Apk[r][1], w1, 0ull));
                float alo, ahi;
                unpk2(acc, alo, ahi);
                vals[r] = alo + ahi;
            }

            // 16 values across 32 lanes -> lane holds row rl = (lane>>1)&15.
            #pragma unroll
            for (int st = 0; st < 4; ++st) {
                const int msk = 16 >> st;       // 16, 8, 4, 2
                const int h   = 8 >> st;        //  8, 4, 2, 1
                const bool hi = (lane & msk) != 0;
                #pragma unroll
                for (int k = 0; k < 8; ++k) {   // only k < h active
                    if (k < h) {
                        const float send = hi ? vals[k] : vals[k + h];
                        const float got  = __shfl_xor_sync(0xffffffffu, send, msk);
                        vals[k] = (hi ? vals[k + h] : vals[k]) + got;
                    }
                }
            }
            vals[0] += __shfl_xor_sync(0xffffffffu, vals[0], 1);

            // publish per-(rowgroup, colgroup) partial: us[i][rl][j], pad 5
            if ((lane & 1) == 0)
                us[i * 80 + rl * 5 + j] = vals[0];
        }
        __syncthreads();   // bar3

        // ========== u update (in-register, per-lane row rl) ================
        {
            const float* usr = &us[i * 80 + rl * 5];
            const float y = (usr[0] + usr[1]) + (usr[2] + usr[3]);
            ureg = fmaf(BETA, y - breg, ureg);
        }
        // no trailing bar: next pass1 uses warp-local shfl of ureg; us is
        // rewritten only after the next iteration's bar2.
    }

    // ---- Output: rank-0 CTA writes its batch's x ----
    if (rank == 0)
        out[batch * N + tid] = xreg;
}

extern "C" void kernel_launch(void* const* d_in, const int* in_sizes, int n_in,
                              void* d_out, int out_size)
{
    (void)in_sizes; (void)n_in; (void)out_size;
    const float* A = (const float*)d_in[0];
    const float* b = (const float*)d_in[1];
    float* out = (float*)d_out;

    pdhg_kernel<<<BS * CLUSTER, THREADS>>>(A, b, out);
}